// round 5
// baseline (speedup 1.0000x reference)
#include <cuda_runtime.h>

#define N_VERTS 53215
#define EXP_DIM 29
#define SHP_DIM 199
#define SHP3    (3 * SHP_DIM)   // 597
#define EXP3    (3 * EXP_DIM)   // 87

#define NTHREADS 256
#define VPT 16                          // vertices per block tile
#define SHP_F (VPT * SHP3)              // 9552 floats (38208 B, 16B-aligned tiles)
#define EXP_F (VPT * EXP3)              // 1392 floats (5568 B, 16B-aligned tiles)
#define N_TILES ((N_VERTS + VPT - 1) / VPT)   // 3326

// ---------------------------------------------------------------------------
// Tile-staged fused kernel.
// Phase 1: block cooperatively streams a 16-vertex tile (w_shp: 38.2KB,
//          w_exp: 5.6KB) into shared memory with LDG.128 (float4) — tile
//          bases are 16B-aligned because 16*597*4 and 16*87*4 are both
//          multiples of 16. Alphas also staged to smem.
// Phase 2: each of 8 warps computes 2 vertices: coalesced LDS passes over the
//          vertex's contiguous 597/87-float block, alpha from smem
//          (consecutive banks, conflict-free), compile-time row routing,
//          3 warp reductions, closed-form transform, direct store.
//
// Transform (derived from _transform_matrix(pose, 450)):
//   s  = p3 + p7 + p11
//   ox = ( s*(p0x + p1y + p2z)  + p3)        * (224/450)
//   oy = (-s*(p4x + p5y + p6z)  - p7 + 450)  * (224/450)
//   oz =   s*(p8x + p9y + p10z)
// ---------------------------------------------------------------------------
__global__ void __launch_bounds__(NTHREADS)
pca_tile_kernel(const float* __restrict__ pose,
                const float* __restrict__ a_exp,
                const float* __restrict__ a_shp,
                const float* __restrict__ u,
                const float* __restrict__ w_exp,
                const float* __restrict__ w_shp,
                float* __restrict__ out)
{
    __shared__ float s_shp[SHP_F];
    __shared__ float s_exp[EXP_F];
    __shared__ float s_as[SHP_DIM];
    __shared__ float s_ae[EXP_DIM];

    const int t      = threadIdx.x;
    const int tile   = blockIdx.x;
    const int v_base = tile * VPT;
    const int nv     = (N_VERTS - v_base < VPT) ? (N_VERTS - v_base) : VPT;

    // ---- stage alphas ----
    for (int i = t; i < SHP_DIM; i += NTHREADS) s_as[i] = a_shp[i];
    if (t < EXP_DIM) s_ae[t] = a_exp[t];

    // ---- stage w tiles (vectorized for full tiles) ----
    if (nv == VPT) {
        const float4* __restrict__ g4 = (const float4*)(w_shp + (size_t)v_base * SHP3);
        float4* s4 = (float4*)s_shp;
        #pragma unroll
        for (int i = t; i < SHP_F / 4; i += NTHREADS) s4[i] = g4[i];

        const float4* __restrict__ ge4 = (const float4*)(w_exp + (size_t)v_base * EXP3);
        float4* se4 = (float4*)s_exp;
        #pragma unroll
        for (int i = t; i < EXP_F / 4; i += NTHREADS) se4[i] = ge4[i];
    } else {
        const float* __restrict__ g = w_shp + (size_t)v_base * SHP3;
        for (int i = t; i < nv * SHP3; i += NTHREADS) s_shp[i] = g[i];
        const float* __restrict__ ge = w_exp + (size_t)v_base * EXP3;
        for (int i = t; i < nv * EXP3; i += NTHREADS) s_exp[i] = ge[i];
    }
    __syncthreads();

    // ---- compute: warp wid handles local vertices 2*wid, 2*wid+1 ----
    const int wid  = t >> 5;
    const int lane = t & 31;

    #pragma unroll
    for (int k = 0; k < 2; k++) {
        const int lv = 2 * wid + k;
        if (lv >= nv) continue;
        const int v = v_base + lv;

        const float* __restrict__ ws = s_shp + lv * SHP3;
        const float* __restrict__ we = s_exp + lv * EXP3;

        float a0 = 0.f, a1 = 0.f, a2 = 0.f;

        #pragma unroll
        for (int i = 0; i < 19; i++) {
            const int j = i * 32 + lane;
            if (j < SHP3) {
                int col;
                if (j < SHP_DIM)          col = j;
                else if (j < 2 * SHP_DIM) col = j - SHP_DIM;
                else                      col = j - 2 * SHP_DIM;
                const float p = ws[j] * s_as[col];
                if (j < SHP_DIM)          a0 += p;
                else if (j < 2 * SHP_DIM) a1 += p;
                else                      a2 += p;
            }
        }
        #pragma unroll
        for (int i = 0; i < 3; i++) {
            const int j = i * 32 + lane;
            if (j < EXP3) {
                int col;
                if (j < EXP_DIM)          col = j;
                else if (j < 2 * EXP_DIM) col = j - EXP_DIM;
                else                      col = j - 2 * EXP_DIM;
                const float p = we[j] * s_ae[col];
                if (j < EXP_DIM)          a0 += p;
                else if (j < 2 * EXP_DIM) a1 += p;
                else                      a2 += p;
            }
        }

        #pragma unroll
        for (int off = 16; off > 0; off >>= 1) {
            a0 += __shfl_down_sync(0xffffffffu, a0, off);
            a1 += __shfl_down_sync(0xffffffffu, a1, off);
            a2 += __shfl_down_sync(0xffffffffu, a2, off);
        }

        if (lane == 0) {
            const float p0 = __ldg(pose + 0),  p1 = __ldg(pose + 1),  p2  = __ldg(pose + 2),  p3  = __ldg(pose + 3);
            const float p4 = __ldg(pose + 4),  p5 = __ldg(pose + 5),  p6  = __ldg(pose + 6),  p7  = __ldg(pose + 7);
            const float p8 = __ldg(pose + 8),  p9 = __ldg(pose + 9),  p10 = __ldg(pose + 10), p11 = __ldg(pose + 11);
            const float s  = p3 + p7 + p11;
            const float aspect_xy = 224.0f / 450.0f;

            const float x = a0 + __ldg(u + 3 * v + 0);
            const float y = a1 + __ldg(u + 3 * v + 1);
            const float z = a2 + __ldg(u + 3 * v + 2);

            out[3 * v + 0] = ( s * (p0 * x + p1 * y + p2  * z) + p3)          * aspect_xy;
            out[3 * v + 1] = (-s * (p4 * x + p5 * y + p6  * z) - p7 + 450.0f) * aspect_xy;
            out[3 * v + 2] =   s * (p8 * x + p9 * y + p10 * z);
        }
    }
}

// ---------------------------------------------------------------------------
// Entry point
// Input order: pose_3DMM, alpha_exp, alpha_shp, u_base, w_exp_base, w_shp_base
// ---------------------------------------------------------------------------
extern "C" void kernel_launch(void* const* d_in, const int* in_sizes, int n_in,
                              void* d_out, int out_size)
{
    const float* pose  = (const float*)d_in[0];
    const float* a_exp = (const float*)d_in[1];
    const float* a_shp = (const float*)d_in[2];
    const float* u     = (const float*)d_in[3];
    const float* w_exp = (const float*)d_in[4];
    const float* w_shp = (const float*)d_in[5];
    float* out = (float*)d_out;

    pca_tile_kernel<<<N_TILES, NTHREADS>>>(pose, a_exp, a_shp, u, w_exp, w_shp, out);
}

// round 6
// speedup vs baseline: 1.3465x; 1.3465x over previous
#include <cuda_runtime.h>

#define N_VERTS 53215
#define EXP_DIM 29
#define SHP_DIM 199
#define SHP3    (3 * SHP_DIM)   // 597
#define EXP3    (3 * EXP_DIM)   // 87

#define NTHREADS 256
#define WARPS_PER_BLOCK (NTHREADS / 32)

// ---------------------------------------------------------------------------
// R2 skeleton (warp-per-vertex, 6652 blocks) + explicit front-batched loads.
//
// All 22 streaming w-loads (19 shp passes + 3 exp passes) are issued into a
// register array BEFORE any dependent FMA, so ptxas emits one batched LDG
// block per warp (MLP ~22) and the warp pays ~one DRAM round-trip instead of
// several. Alpha gathers stay in the FMA phase (L1-resident after warm-up,
// consecutive-lane coalesced).
//
// Transform (derived from _transform_matrix(pose, 450)):
//   s  = p3 + p7 + p11
//   ox = ( s*(p0x + p1y + p2z)  + p3)        * (224/450)
//   oy = (-s*(p4x + p5y + p6z)  - p7 + 450)  * (224/450)
//   oz =   s*(p8x + p9y + p10z)
// ---------------------------------------------------------------------------
__global__ void __launch_bounds__(NTHREADS)
pca_batched_kernel(const float* __restrict__ pose,
                   const float* __restrict__ a_exp,
                   const float* __restrict__ a_shp,
                   const float* __restrict__ u,
                   const float* __restrict__ w_exp,
                   const float* __restrict__ w_shp,
                   float* __restrict__ out)
{
    const int warp = (blockIdx.x * blockDim.x + threadIdx.x) >> 5;
    const int lane = threadIdx.x & 31;
    if (warp >= N_VERTS) return;

    const float* __restrict__ ws = w_shp + (size_t)warp * SHP3;
    const float* __restrict__ we = w_exp + (size_t)warp * EXP3;

    // ---- phase 1: front-batched independent loads (MLP ~= 22) ----
    float w[22];
    #pragma unroll
    for (int i = 0; i < 19; i++) {
        const int j = i * 32 + lane;
        w[i] = (j < SHP3) ? ws[j] : 0.0f;
    }
    #pragma unroll
    for (int i = 0; i < 3; i++) {
        const int j = i * 32 + lane;
        w[19 + i] = (j < EXP3) ? we[j] : 0.0f;
    }

    // ---- phase 2: products with alpha gathers (L1 hits), row routing ----
    float a0 = 0.f, a1 = 0.f, a2 = 0.f;

    #pragma unroll
    for (int i = 0; i < 19; i++) {
        const int j = i * 32 + lane;
        if (j < SHP3) {
            int col;
            if (j < SHP_DIM)          col = j;
            else if (j < 2 * SHP_DIM) col = j - SHP_DIM;
            else                      col = j - 2 * SHP_DIM;
            const float p = w[i] * __ldg(a_shp + col);
            if (j < SHP_DIM)          a0 += p;
            else if (j < 2 * SHP_DIM) a1 += p;
            else                      a2 += p;
        }
    }
    #pragma unroll
    for (int i = 0; i < 3; i++) {
        const int j = i * 32 + lane;
        if (j < EXP3) {
            int col;
            if (j < EXP_DIM)          col = j;
            else if (j < 2 * EXP_DIM) col = j - EXP_DIM;
            else                      col = j - 2 * EXP_DIM;
            const float p = w[19 + i] * __ldg(a_exp + col);
            if (j < EXP_DIM)          a0 += p;
            else if (j < 2 * EXP_DIM) a1 += p;
            else                      a2 += p;
        }
    }

    // ---- warp reductions (3 values) ----
    #pragma unroll
    for (int off = 16; off > 0; off >>= 1) {
        a0 += __shfl_down_sync(0xffffffffu, a0, off);
        a1 += __shfl_down_sync(0xffffffffu, a1, off);
        a2 += __shfl_down_sync(0xffffffffu, a2, off);
    }

    if (lane == 0) {
        const float p0 = __ldg(pose + 0),  p1 = __ldg(pose + 1),  p2  = __ldg(pose + 2),  p3  = __ldg(pose + 3);
        const float p4 = __ldg(pose + 4),  p5 = __ldg(pose + 5),  p6  = __ldg(pose + 6),  p7  = __ldg(pose + 7);
        const float p8 = __ldg(pose + 8),  p9 = __ldg(pose + 9),  p10 = __ldg(pose + 10), p11 = __ldg(pose + 11);
        const float s  = p3 + p7 + p11;
        const float aspect_xy = 224.0f / 450.0f;

        const float x = a0 + __ldg(u + 3 * warp + 0);
        const float y = a1 + __ldg(u + 3 * warp + 1);
        const float z = a2 + __ldg(u + 3 * warp + 2);

        out[3 * warp + 0] = ( s * (p0 * x + p1 * y + p2  * z) + p3)          * aspect_xy;
        out[3 * warp + 1] = (-s * (p4 * x + p5 * y + p6  * z) - p7 + 450.0f) * aspect_xy;
        out[3 * warp + 2] =   s * (p8 * x + p9 * y + p10 * z);
    }
}

// ---------------------------------------------------------------------------
// Entry point
// Input order: pose_3DMM, alpha_exp, alpha_shp, u_base, w_exp_base, w_shp_base
// ---------------------------------------------------------------------------
extern "C" void kernel_launch(void* const* d_in, const int* in_sizes, int n_in,
                              void* d_out, int out_size)
{
    const float* pose  = (const float*)d_in[0];
    const float* a_exp = (const float*)d_in[1];
    const float* a_shp = (const float*)d_in[2];
    const float* u     = (const float*)d_in[3];
    const float* w_exp = (const float*)d_in[4];
    const float* w_shp = (const float*)d_in[5];
    float* out = (float*)d_out;

    const int blocks = (N_VERTS + WARPS_PER_BLOCK - 1) / WARPS_PER_BLOCK;
    pca_batched_kernel<<<blocks, NTHREADS>>>(pose, a_exp, a_shp, u, w_exp, w_shp, out);
}

// round 7
// speedup vs baseline: 1.5033x; 1.1165x over previous
#include <cuda_runtime.h>

#define N_VERTS 53215
#define EXP_DIM 29
#define SHP_DIM 199
#define SHP3    (3 * SHP_DIM)   // 597
#define EXP3    (3 * EXP_DIM)   // 87

#define NTHREADS 256
#define WARPS_PER_BLOCK (NTHREADS / 32)

// ---------------------------------------------------------------------------
// R2 skeleton + FORCED front-batched loads.
//
// __syncwarp() between the load phase and the compute phase makes all 22
// streamed values live across a barrier, so ptxas must allocate 22 distinct
// registers and emit the loads back-to-back (MLP ~22/warp) instead of
// interleaving load+FMA pairs in a 32-reg budget (what R2/R6 compiled to).
// __launch_bounds__(256, 4) raises the register target to make room.
// Compute phase is branch-free: alpha columns are clamped (w is zero-filled
// on out-of-range lanes, so the clamped alpha value never affects the sum).
//
// Transform (derived from _transform_matrix(pose, 450)):
//   s  = p3 + p7 + p11
//   ox = ( s*(p0x + p1y + p2z)  + p3)        * (224/450)
//   oy = (-s*(p4x + p5y + p6z)  - p7 + 450)  * (224/450)
//   oz =   s*(p8x + p9y + p10z)
// ---------------------------------------------------------------------------
__global__ void __launch_bounds__(NTHREADS, 4)
pca_mlp_kernel(const float* __restrict__ pose,
               const float* __restrict__ a_exp,
               const float* __restrict__ a_shp,
               const float* __restrict__ u,
               const float* __restrict__ w_exp,
               const float* __restrict__ w_shp,
               float* __restrict__ out)
{
    const int warp = (blockIdx.x * blockDim.x + threadIdx.x) >> 5;
    const int lane = threadIdx.x & 31;
    if (warp >= N_VERTS) return;

    const float* __restrict__ ws = w_shp + (size_t)warp * SHP3;
    const float* __restrict__ we = w_exp + (size_t)warp * EXP3;

    // ---- phase 1: front-batched independent loads (forced live: 22 regs) ----
    float w[22];
    #pragma unroll
    for (int i = 0; i < 19; i++) {
        const int j = i * 32 + lane;
        w[i] = (j < SHP3) ? __ldcs(ws + j) : 0.0f;
    }
    #pragma unroll
    for (int i = 0; i < 3; i++) {
        const int j = i * 32 + lane;
        w[19 + i] = (j < EXP3) ? __ldcs(we + j) : 0.0f;
    }

    __syncwarp();   // all w[] live across this point -> ptxas must batch loads

    // ---- phase 2: branch-free products + row routing ----
    float a0 = 0.f, a1 = 0.f, a2 = 0.f;

    #pragma unroll
    for (int i = 0; i < 19; i++) {
        const int j = i * 32 + lane;
        int col, row;
        if (j < SHP_DIM)          { col = j;               row = 0; }
        else if (j < 2 * SHP_DIM) { col = j - SHP_DIM;     row = 1; }
        else                      { col = j - 2 * SHP_DIM; row = 2; }
        if (col > SHP_DIM - 1) col = SHP_DIM - 1;   // w==0 there; keep read in-bounds
        const float p = w[i] * __ldg(a_shp + col);
        if (row == 0)      a0 += p;
        else if (row == 1) a1 += p;
        else               a2 += p;
    }
    #pragma unroll
    for (int i = 0; i < 3; i++) {
        const int j = i * 32 + lane;
        int col, row;
        if (j < EXP_DIM)          { col = j;               row = 0; }
        else if (j < 2 * EXP_DIM) { col = j - EXP_DIM;     row = 1; }
        else                      { col = j - 2 * EXP_DIM; row = 2; }
        if (col > EXP_DIM - 1) col = EXP_DIM - 1;
        const float p = w[19 + i] * __ldg(a_exp + col);
        if (row == 0)      a0 += p;
        else if (row == 1) a1 += p;
        else               a2 += p;
    }

    // ---- warp reductions (3 values) ----
    #pragma unroll
    for (int off = 16; off > 0; off >>= 1) {
        a0 += __shfl_down_sync(0xffffffffu, a0, off);
        a1 += __shfl_down_sync(0xffffffffu, a1, off);
        a2 += __shfl_down_sync(0xffffffffu, a2, off);
    }

    if (lane == 0) {
        const float p0 = __ldg(pose + 0),  p1 = __ldg(pose + 1),  p2  = __ldg(pose + 2),  p3  = __ldg(pose + 3);
        const float p4 = __ldg(pose + 4),  p5 = __ldg(pose + 5),  p6  = __ldg(pose + 6),  p7  = __ldg(pose + 7);
        const float p8 = __ldg(pose + 8),  p9 = __ldg(pose + 9),  p10 = __ldg(pose + 10), p11 = __ldg(pose + 11);
        const float s  = p3 + p7 + p11;
        const float aspect_xy = 224.0f / 450.0f;

        const float x = a0 + __ldg(u + 3 * warp + 0);
        const float y = a1 + __ldg(u + 3 * warp + 1);
        const float z = a2 + __ldg(u + 3 * warp + 2);

        out[3 * warp + 0] = ( s * (p0 * x + p1 * y + p2  * z) + p3)          * aspect_xy;
        out[3 * warp + 1] = (-s * (p4 * x + p5 * y + p6  * z) - p7 + 450.0f) * aspect_xy;
        out[3 * warp + 2] =   s * (p8 * x + p9 * y + p10 * z);
    }
}

// ---------------------------------------------------------------------------
// Entry point
// Input order: pose_3DMM, alpha_exp, alpha_shp, u_base, w_exp_base, w_shp_base
// ---------------------------------------------------------------------------
extern "C" void kernel_launch(void* const* d_in, const int* in_sizes, int n_in,
                              void* d_out, int out_size)
{
    const float* pose  = (const float*)d_in[0];
    const float* a_exp = (const float*)d_in[1];
    const float* a_shp = (const float*)d_in[2];
    const float* u     = (const float*)d_in[3];
    const float* w_exp = (const float*)d_in[4];
    const float* w_shp = (const float*)d_in[5];
    float* out = (float*)d_out;

    const int blocks = (N_VERTS + WARPS_PER_BLOCK - 1) / WARPS_PER_BLOCK;
    pca_mlp_kernel<<<blocks, NTHREADS>>>(pose, a_exp, a_shp, u, w_exp, w_shp, out);
}